// round 7
// baseline (speedup 1.0000x reference)
#include <cuda_runtime.h>
#include <cuda_bf16.h>
#include <math.h>

// Problem constants (fixed by the reference)
#define NPSD   256          // L*D = flat node repr dim
#define SINT   32           // intersection set size
#define RELD_  32
#define INPF   32           // node_feat dim
#define DD     64           // dist emb dim
#define GDIM   864          // g_rep dim: 256+256+32+256+32+32

#define BMAX   16384
__device__ float g_mid[BMAX * NPSD];   // mid_repr scratch [B, 256]

// ===================== k1: high-occupancy masked-mean gather =====================
#define K1LPB  4
__global__ void __launch_bounds__(256) gcw_gather(
    const float* __restrict__ flat,   // [N, 256]
    const int*   __restrict__ inter,  // [B, 32]
    int B)
{
    __shared__ int2 spack[K1LPB * SINT];   // (row_off, weight)

    const int t  = threadIdx.x;
    const int b0 = blockIdx.x * K1LPB;

    // warps 0..3: warp w computes descriptors for link w
    if (t < K1LPB * SINT) {
        int l = t >> 5, s = t & 31;
        int b = min(b0 + l, B - 1);
        int c = inter[(long)b * SINT + s];
        unsigned m = __ballot_sync(0xFFFFFFFFu, c != -1);
        float inv = 1.f / (float)max(__popc(m), 1);
        float w = (float)((c > -1) - (c < -1)) * inv;   // sign(c+1)/cnt
        spack[t] = make_int2((c < 0 ? -c : c) * NPSD, __float_as_int(w));
    }
    __syncthreads();

    const int l  = t >> 6;            // 0..3
    const int c4 = (t & 63) * 4;
    const float* fc4 = flat + c4;
    const int2* spk = spack + l * SINT;

    float4 a0 = make_float4(0.f, 0.f, 0.f, 0.f);
    float4 a1 = make_float4(0.f, 0.f, 0.f, 0.f);
    float4 a2 = make_float4(0.f, 0.f, 0.f, 0.f);
    float4 a3 = make_float4(0.f, 0.f, 0.f, 0.f);

    #pragma unroll
    for (int s = 0; s < SINT; s += 4) {
        int2 p0 = spk[s];
        int2 p1 = spk[s + 1];
        int2 p2 = spk[s + 2];
        int2 p3 = spk[s + 3];
        const float4 v0 = __ldcs((const float4*)(fc4 + p0.x));
        const float4 v1 = __ldcs((const float4*)(fc4 + p1.x));
        const float4 v2 = __ldcs((const float4*)(fc4 + p2.x));
        const float4 v3 = __ldcs((const float4*)(fc4 + p3.x));
        float w0 = __int_as_float(p0.y);
        float w1 = __int_as_float(p1.y);
        float w2 = __int_as_float(p2.y);
        float w3 = __int_as_float(p3.y);
        a0.x = fmaf(v0.x, w0, a0.x); a0.y = fmaf(v0.y, w0, a0.y);
        a0.z = fmaf(v0.z, w0, a0.z); a0.w = fmaf(v0.w, w0, a0.w);
        a1.x = fmaf(v1.x, w1, a1.x); a1.y = fmaf(v1.y, w1, a1.y);
        a1.z = fmaf(v1.z, w1, a1.z); a1.w = fmaf(v1.w, w1, a1.w);
        a2.x = fmaf(v2.x, w2, a2.x); a2.y = fmaf(v2.y, w2, a2.y);
        a2.z = fmaf(v2.z, w2, a2.z); a2.w = fmaf(v2.w, w2, a2.w);
        a3.x = fmaf(v3.x, w3, a3.x); a3.y = fmaf(v3.y, w3, a3.y);
        a3.z = fmaf(v3.z, w3, a3.z); a3.w = fmaf(v3.w, w3, a3.w);
    }

    int b = b0 + l;
    if (b < B) {
        float4 r;
        r.x = (a0.x + a1.x) + (a2.x + a3.x);
        r.y = (a0.y + a1.y) + (a2.y + a3.y);
        r.z = (a0.z + a1.z) + (a2.z + a3.z);
        r.w = (a0.w + a1.w) + (a2.w + a3.w);
        *(float4*)&g_mid[(long)b * NPSD + c4] = r;
    }
}

// ===================== k2: fused GEMMs =====================
#define LPB    8            // links per block
#define NTHR   256

// shared layout (floats):
//  sg    : LPB*GDIM = 6912
//  sdist : LPB*64   = 512
//  sh1   : LPB*64   = 512
//  sh2   : LPB*32   = 256
//  red   : 8*8*64   = 4096
//  shead/stail/srel/sdi : 4*LPB = 32 ints
#define SMEM_FLOATS (LPB*GDIM + LPB*64 + LPB*64 + LPB*32 + 8*LPB*64)
#define SMEM_INTS   (4*LPB)
#define SMEM_BYTES  ((SMEM_FLOATS + SMEM_INTS) * 4)

__global__ void __launch_bounds__(NTHR, 3) gcw_fused(
    const float* __restrict__ flat,      // [N, 256]
    const float* __restrict__ feat,      // [N, 32]
    const int*   __restrict__ head_idx,  // [B]
    const int*   __restrict__ rel_idx,   // [B]
    const int*   __restrict__ tail_idx,  // [B]
    const int*   __restrict__ dist_idx,  // [B]
    const float* __restrict__ rel_emb,   // [200, 32]
    const float* __restrict__ dist_emb,  // [11, 64]
    const float* __restrict__ headW,     // [320, 32]
    const float* __restrict__ headb,     // [32]
    const float* __restrict__ tailW,     // [320, 32]
    const float* __restrict__ tailb,     // [32]
    const float* __restrict__ W1,        // [864, 64]
    const float* __restrict__ b1,        // [64]
    const float* __restrict__ W2,        // [64, 32]
    const float* __restrict__ b2,        // [32]
    const float* __restrict__ W3,        // [32, 1]
    const float* __restrict__ b3,        // [1]
    float* __restrict__ out, int B)
{
    extern __shared__ float sh[];
    float* sg    = sh;                          // [LPB][GDIM]
    float* sdist = sg    + LPB * GDIM;          // [LPB][64]
    float* sh1   = sdist + LPB * 64;            // [LPB][64]
    float* sh2   = sh1   + LPB * 64;            // [LPB][32]
    float* red   = sh2   + LPB * 32;            // [8][LPB][64]
    int*   shead = (int*)(red + 8 * LPB * 64);
    int*   stail = shead + LPB;
    int*   srel  = stail + LPB;
    int*   sdi   = srel  + LPB;

    const int t  = threadIdx.x;
    const int b0 = blockIdx.x * LPB;

    // ---- load per-link indices ----
    if (t < LPB) {
        int b = min(b0 + t, B - 1);
        shead[t] = head_idx[b];
        stail[t] = tail_idx[b];
        srel[t]  = rel_idx[b];
        sdi[t]   = dist_idx[b];
    }
    __syncthreads();

    const int g  = t >> 6;          // 0..3
    const int c4 = (t & 63) * 4;    // float4 column base within 256

    // ---- gather head/tail reprs + mid from scratch ----
    #pragma unroll
    for (int li = 0; li < 2; li++) {
        int l = g + li * 4;
        int b = min(b0 + l, B - 1);
        float4 h  = __ldcs((const float4*)&flat[(long)shead[l] * NPSD + c4]);
        float4 tl = __ldcs((const float4*)&flat[(long)stail[l] * NPSD + c4]);
        float4 m  = *(const float4*)&g_mid[(long)b * NPSD + c4];
        *(float4*)&sg[l * GDIM + c4]       = h;
        *(float4*)&sg[l * GDIM + 256 + c4] = tl;
        *(float4*)&sg[l * GDIM + 544 + c4] = m;
    }
    // rel_repr, head/tail feats  (LPB*32 == NTHR)
    {
        int l = t >> 5, j = t & 31;
        sg[l * GDIM + 512 + j] = rel_emb[(long)srel[l] * RELD_ + j];
        sg[l * GDIM + 800 + j] = feat[(long)shead[l] * INPF + j];
        sg[l * GDIM + 832 + j] = feat[(long)stail[l] * INPF + j];
    }
    // dist_repr (LPB*64 = 512 -> 2 reps)
    #pragma unroll
    for (int rep = 0; rep < 2; rep++) {
        int u = rep * NTHR + t;
        int l = u >> 6, j = u & 63;
        sdist[l * 64 + j] = dist_emb[(long)sdi[l] * DD + j];
    }
    __syncthreads();

    // ---- emit head/tail init feats from smem (LPB*32 == NTHR) ----
    {
        long hf = (long)B + 2L * B * 32;
        long tf = (long)B + 3L * B * 32;
        int l = t >> 5, j = t & 31;
        int b = b0 + l;
        if (b < B) {
            out[hf + (long)b * 32 + j] = sg[l * GDIM + 800 + j];
            out[tf + (long)b * 32 + j] = sg[l * GDIM + 832 + j];
        }
    }

    // ---- head/tail pred: md[320] @ W[320,32], jtile=2, 8-way split-K ----
    {
        const int jj2 = (t & 15) * 2;        // 0,2,...,30
        const int sel = (t >> 4) & 1;        // 0=head, 1=tail
        const int q   = t >> 5;              // 0..7
        const float* W = sel ? tailW : headW;
        float acc[LPB][2];
        #pragma unroll
        for (int l = 0; l < LPB; l++) { acc[l][0] = 0.f; acc[l][1] = 0.f; }

        const int k0 = q * 40;
        #pragma unroll
        for (int kk = 0; kk < 40; kk += 4) {
            const int k = k0 + kk;
            float2 w0 = *(const float2*)&W[(k    ) * INPF + jj2];
            float2 w1 = *(const float2*)&W[(k + 1) * INPF + jj2];
            float2 w2 = *(const float2*)&W[(k + 2) * INPF + jj2];
            float2 w3 = *(const float2*)&W[(k + 3) * INPF + jj2];
            #pragma unroll
            for (int l = 0; l < LPB; l++) {
                float4 m;
                if (k < 256) m = *(const float4*)&sg[l * GDIM + 544 + k];
                else         m = *(const float4*)&sdist[l * 64 + (k - 256)];
                acc[l][0] = fmaf(m.x, w0.x, acc[l][0]);
                acc[l][1] = fmaf(m.x, w0.y, acc[l][1]);
                acc[l][0] = fmaf(m.y, w1.x, acc[l][0]);
                acc[l][1] = fmaf(m.y, w1.y, acc[l][1]);
                acc[l][0] = fmaf(m.z, w2.x, acc[l][0]);
                acc[l][1] = fmaf(m.z, w2.y, acc[l][1]);
                acc[l][0] = fmaf(m.w, w3.x, acc[l][0]);
                acc[l][1] = fmaf(m.w, w3.y, acc[l][1]);
            }
        }
        #pragma unroll
        for (int l = 0; l < LPB; l++)
            *(float2*)&red[q * 512 + l * 64 + sel * 32 + jj2] =
                make_float2(acc[l][0], acc[l][1]);
    }
    __syncthreads();

    // ---- reduce pred partials + bias -> out ----
    #pragma unroll
    for (int rep = 0; rep < 2; rep++) {
        int p = rep * NTHR + t;
        int l = p >> 6, j = p & 63, jj = j & 31;
        float s = 0.f;
        #pragma unroll
        for (int q = 0; q < 8; q++) s += red[q * 512 + l * 64 + j];
        int b = b0 + l;
        if (b < B) {
            if (j < 32) out[B + (long)b * 32 + jj] = s + headb[jj];
            else        out[B + (long)B * 32 + (long)b * 32 + jj] = s + tailb[jj];
        }
    }
    __syncthreads();   // red reused below

    // ---- W1: g_rep[864] @ W1[864,64], jtile=2, 8-way split-K ----
    {
        const int j2 = (t & 31) * 2;         // 0,2,...,62
        const int q  = t >> 5;               // 0..7
        float acc[LPB][2];
        #pragma unroll
        for (int l = 0; l < LPB; l++) { acc[l][0] = 0.f; acc[l][1] = 0.f; }

        const int k0 = q * 108;
        #pragma unroll 3
        for (int k = k0; k < k0 + 108; k += 4) {
            float2 w0 = *(const float2*)&W1[(k    ) * 64 + j2];
            float2 w1 = *(const float2*)&W1[(k + 1) * 64 + j2];
            float2 w2 = *(const float2*)&W1[(k + 2) * 64 + j2];
            float2 w3 = *(const float2*)&W1[(k + 3) * 64 + j2];
            #pragma unroll
            for (int l = 0; l < LPB; l++) {
                const float4 gg = *(const float4*)&sg[l * GDIM + k];
                acc[l][0] = fmaf(gg.x, w0.x, acc[l][0]);
                acc[l][1] = fmaf(gg.x, w0.y, acc[l][1]);
                acc[l][0] = fmaf(gg.y, w1.x, acc[l][0]);
                acc[l][1] = fmaf(gg.y, w1.y, acc[l][1]);
                acc[l][0] = fmaf(gg.z, w2.x, acc[l][0]);
                acc[l][1] = fmaf(gg.z, w2.y, acc[l][1]);
                acc[l][0] = fmaf(gg.w, w3.x, acc[l][0]);
                acc[l][1] = fmaf(gg.w, w3.y, acc[l][1]);
            }
        }
        #pragma unroll
        for (int l = 0; l < LPB; l++)
            *(float2*)&red[q * 512 + l * 64 + j2] = make_float2(acc[l][0], acc[l][1]);
    }
    __syncthreads();

    // ---- reduce W1 partials + bias + relu -> sh1 ----
    #pragma unroll
    for (int rep = 0; rep < 2; rep++) {
        int p = rep * NTHR + t;
        int l = p >> 6, j = p & 63;
        float s = 0.f;
        #pragma unroll
        for (int q = 0; q < 8; q++) s += red[q * 512 + l * 64 + j];
        sh1[l * 64 + j] = fmaxf(s + b1[j], 0.f);
    }
    __syncthreads();

    // ---- W2: h1[64] @ W2[64,32] + relu (LPB*32 == NTHR) ----
    {
        int j = t & 31, l = t >> 5;
        float a = 0.f;
        #pragma unroll
        for (int k = 0; k < 64; k += 4) {
            float w0 = W2[(k    ) * 32 + j];
            float w1 = W2[(k + 1) * 32 + j];
            float w2 = W2[(k + 2) * 32 + j];
            float w3 = W2[(k + 3) * 32 + j];
            const float4 h = *(const float4*)&sh1[l * 64 + k];
            a = fmaf(h.x, w0, a);
            a = fmaf(h.y, w1, a);
            a = fmaf(h.z, w2, a);
            a = fmaf(h.w, w3, a);
        }
        sh2[l * 32 + j] = fmaxf(a + b2[j], 0.f);
    }
    __syncthreads();

    // ---- W3: h2[32] @ W3[32,1] -> out[b] (8 warps, 1 link each) ----
    {
        int w = t >> 5, lane = t & 31;
        float v = sh2[w * 32 + lane] * W3[lane];
        #pragma unroll
        for (int off = 16; off > 0; off >>= 1)
            v += __shfl_xor_sync(0xFFFFFFFFu, v, off);
        if (lane == 0 && (b0 + w) < B)
            out[b0 + w] = v + b3[0];
    }
}

extern "C" void kernel_launch(void* const* d_in, const int* in_sizes, int n_in,
                              void* d_out, int out_size)
{
    const float* flat     = (const float*)d_in[0];
    const float* feat     = (const float*)d_in[1];
    const int*   head_idx = (const int*)  d_in[2];
    const int*   rel_idx  = (const int*)  d_in[3];
    const int*   tail_idx = (const int*)  d_in[4];
    const int*   dist_idx = (const int*)  d_in[5];
    const int*   inter    = (const int*)  d_in[6];
    const float* rel_emb  = (const float*)d_in[7];
    const float* dist_emb = (const float*)d_in[8];
    const float* headW    = (const float*)d_in[9];
    const float* headb    = (const float*)d_in[10];
    const float* tailW    = (const float*)d_in[11];
    const float* tailb    = (const float*)d_in[12];
    const float* W1       = (const float*)d_in[13];
    const float* b1       = (const float*)d_in[14];
    const float* W2       = (const float*)d_in[15];
    const float* b2       = (const float*)d_in[16];
    const float* W3       = (const float*)d_in[17];
    const float* b3       = (const float*)d_in[18];

    int B = in_sizes[2];   // head_idx element count

    // k1: high-occupancy mid gather -> g_mid scratch
    int grid1 = (B + K1LPB - 1) / K1LPB;
    gcw_gather<<<grid1, 256>>>(flat, inter, B);

    // k2: fused GEMMs
    cudaFuncSetAttribute(gcw_fused, cudaFuncAttributeMaxDynamicSharedMemorySize, SMEM_BYTES);
    int grid2 = (B + LPB - 1) / LPB;
    gcw_fused<<<grid2, NTHR, SMEM_BYTES>>>(
        flat, feat, head_idx, rel_idx, tail_idx, dist_idx,
        rel_emb, dist_emb, headW, headb, tailW, tailb,
        W1, b1, W2, b2, W3, b3,
        (float*)d_out, B);
}

// round 8
// speedup vs baseline: 1.0724x; 1.0724x over previous
#include <cuda_runtime.h>
#include <cuda_bf16.h>
#include <math.h>

// Problem constants (fixed by the reference)
#define NPSD   256          // L*D = flat node repr dim
#define SINT   32           // intersection set size
#define RELD_  32
#define INPF   32           // node_feat dim
#define DD     64           // dist emb dim
#define GDIM   864          // g_rep dim: 256+256+32+256+32+32

#define LPB    8            // links per block
#define NTHR   256

// packed f32x2 FMA (Blackwell): lo/hi halves are independent FMAs
#define FMA2(acc, a, b) \
    asm("fma.rn.f32x2 %0, %1, %2, %0;" : "+l"(acc) : "l"(a), "l"(b))

__device__ __forceinline__ float2 upk(unsigned long long u) {
    float2 r;
    asm("mov.b64 {%0, %1}, %2;" : "=f"(r.x), "=f"(r.y) : "l"(u));
    return r;
}

// k-paired weight layouts (filled by gcw_prep):
//   g_wT1[kp][j][2] : (W1[2kp][j], W1[2kp+1][j]),  kp<432, j<64
//   g_wTh/g_wTt[kp][j][2] : same for headW/tailW,  kp<160, j<32
__device__ float g_wT1[432 * 128];
__device__ float g_wTh[160 * 64];
__device__ float g_wTt[160 * 64];

__global__ void gcw_prep(const float* __restrict__ W1,
                         const float* __restrict__ headW,
                         const float* __restrict__ tailW)
{
    int i = blockIdx.x * 256 + threadIdx.x;
    if (i < 432 * 128) {
        int kp = i >> 7, rem = i & 127, j = rem >> 1, r = rem & 1;
        g_wT1[i] = W1[(2 * kp + r) * 64 + j];
    } else if (i < 432 * 128 + 160 * 64) {
        int u = i - 432 * 128;
        int kp = u >> 6, rem = u & 63, j = rem >> 1, r = rem & 1;
        g_wTh[u] = headW[(2 * kp + r) * 32 + j];
    } else if (i < 432 * 128 + 2 * 160 * 64) {
        int u = i - 432 * 128 - 160 * 64;
        int kp = u >> 6, rem = u & 63, j = rem >> 1, r = rem & 1;
        g_wTt[u] = tailW[(2 * kp + r) * 32 + j];
    }
}

// shared layout (floats):
//  sg    : LPB*GDIM = 6912
//  sdist : LPB*64   = 512
//  sh1   : LPB*64   = 512
//  sh2   : LPB*32   = 256
//  red   : 4*8*64   = 2048   (4-way split-K partials)
//  spack : LPB*S int2 = 512 ints ; shead/stail/srel/sdi 4*LPB
#define SMEM_FLOATS (LPB*GDIM + LPB*64 + LPB*64 + LPB*32 + 4*LPB*64)
#define SMEM_INTS   (LPB*SINT*2 + 4*LPB)
#define SMEM_BYTES  ((SMEM_FLOATS + SMEM_INTS) * 4)

__global__ void __launch_bounds__(NTHR, 3) gcw_fused(
    const float* __restrict__ flat,      // [N, 256]
    const float* __restrict__ feat,      // [N, 32]
    const int*   __restrict__ head_idx,  // [B]
    const int*   __restrict__ rel_idx,   // [B]
    const int*   __restrict__ tail_idx,  // [B]
    const int*   __restrict__ dist_idx,  // [B]
    const int*   __restrict__ inter,     // [B, 32]
    const float* __restrict__ rel_emb,   // [200, 32]
    const float* __restrict__ dist_emb,  // [11, 64]
    const float* __restrict__ headb,     // [32]
    const float* __restrict__ tailb,     // [32]
    const float* __restrict__ b1,        // [64]
    const float* __restrict__ W2,        // [64, 32]
    const float* __restrict__ b2,        // [32]
    const float* __restrict__ W3,        // [32, 1]
    const float* __restrict__ b3,        // [1]
    float* __restrict__ out, int B)
{
    extern __shared__ float sh[];
    float* sg    = sh;                          // [LPB][GDIM]
    float* sdist = sg    + LPB * GDIM;          // [LPB][64]
    float* sh1   = sdist + LPB * 64;            // [LPB][64]
    float* sh2   = sh1   + LPB * 64;            // [LPB][32]
    float* red   = sh2   + LPB * 32;            // [4][LPB][64]
    int2*  spack = (int2*)(red + 4 * LPB * 64); // [LPB][S] (row_off, weight)
    int*   shead = (int*)(spack + LPB * SINT);
    int*   stail = shead + LPB;
    int*   srel  = stail + LPB;
    int*   sdi   = srel  + LPB;

    const int t  = threadIdx.x;
    const int b0 = blockIdx.x * LPB;

    // ---- load per-link indices ----
    if (t < LPB) {
        int b = min(b0 + t, B - 1);
        shead[t] = head_idx[b];
        stail[t] = tail_idx[b];
        srel[t]  = rel_idx[b];
        sdi[t]   = dist_idx[b];
    }
    // ---- precompute gather descriptors: warp w <-> link l ----
    {
        int gi = min(b0 * SINT + t, B * SINT - 1);   // LPB*SINT == NTHR
        int c  = inter[gi];
        unsigned m = __ballot_sync(0xFFFFFFFFu, c != -1);
        float inv = 1.f / (float)max(__popc(m), 1);
        float w = (float)((c > -1) - (c < -1)) * inv;    // sign(c+1)/cnt
        spack[t] = make_int2((c < 0 ? -c : c) * NPSD, __float_as_int(w));
    }
    __syncthreads();

    const int g  = t >> 6;          // 0..3
    const int c4 = (t & 63) * 4;    // float4 column base within 256
    const float* flatc4 = flat + c4;

    // ---- gather head/tail reprs (float4, streaming) ----
    #pragma unroll
    for (int li = 0; li < 2; li++) {
        int l = g + li * 4;
        float4 h  = __ldcs((const float4*)&flat[(long)shead[l] * NPSD + c4]);
        float4 tl = __ldcs((const float4*)&flat[(long)stail[l] * NPSD + c4]);
        *(float4*)&sg[l * GDIM + c4]       = h;
        *(float4*)&sg[l * GDIM + 256 + c4] = tl;
    }
    // rel_repr, head/tail feats  (LPB*32 == NTHR)
    {
        int l = t >> 5, j = t & 31;
        sg[l * GDIM + 512 + j] = rel_emb[(long)srel[l] * RELD_ + j];
        sg[l * GDIM + 800 + j] = feat[(long)shead[l] * INPF + j];
        sg[l * GDIM + 832 + j] = feat[(long)stail[l] * INPF + j];
    }
    // dist_repr (LPB*64 = 512 -> 2 reps)
    #pragma unroll
    for (int rep = 0; rep < 2; rep++) {
        int u = rep * NTHR + t;
        int l = u >> 6, j = u & 63;
        sdist[l * 64 + j] = dist_emb[(long)sdi[l] * DD + j];
    }

    // ---- mid: weighted gather-sum (weights pre-folded with 1/cnt) ----
    #pragma unroll
    for (int li = 0; li < 2; li++) {
        int l = g + li * 4;
        const int2* spk = spack + l * SINT;
        float4 a0 = make_float4(0.f, 0.f, 0.f, 0.f);
        float4 a1 = make_float4(0.f, 0.f, 0.f, 0.f);
        #pragma unroll 4
        for (int s = 0; s < SINT; s += 2) {
            int2 p0 = spk[s];
            int2 p1 = spk[s + 1];
            const float4 v0 = __ldcs((const float4*)(flatc4 + p0.x));
            const float4 v1 = __ldcs((const float4*)(flatc4 + p1.x));
            float w0 = __int_as_float(p0.y);
            float w1 = __int_as_float(p1.y);
            a0.x = fmaf(v0.x, w0, a0.x);
            a0.y = fmaf(v0.y, w0, a0.y);
            a0.z = fmaf(v0.z, w0, a0.z);
            a0.w = fmaf(v0.w, w0, a0.w);
            a1.x = fmaf(v1.x, w1, a1.x);
            a1.y = fmaf(v1.y, w1, a1.y);
            a1.z = fmaf(v1.z, w1, a1.z);
            a1.w = fmaf(v1.w, w1, a1.w);
        }
        float4 r;
        r.x = a0.x + a1.x;
        r.y = a0.y + a1.y;
        r.z = a0.z + a1.z;
        r.w = a0.w + a1.w;
        *(float4*)&sg[l * GDIM + 544 + c4] = r;
    }
    __syncthreads();

    // ---- emit head/tail init feats from smem (LPB*32 == NTHR) ----
    {
        long hf = (long)B + 2L * B * 32;
        long tf = (long)B + 3L * B * 32;
        int l = t >> 5, j = t & 31;
        int b = b0 + l;
        if (b < B) {
            out[hf + (long)b * 32 + j] = sg[l * GDIM + 800 + j];
            out[tf + (long)b * 32 + j] = sg[l * GDIM + 832 + j];
        }
    }

    // ---- head/tail pred: md[320] @ W[320,32], f32x2 k-paired ----
    // thread = (jj2:16, sel:2, q:4, lh:2); 4 links, 2 j, 80 ks (40 kpairs)
    {
        const int jj2 = (t & 15) * 2;
        const int sel = (t >> 4) & 1;
        const int q   = (t >> 5) & 3;
        const int lh  = t >> 7;
        const float* wT = sel ? g_wTt : g_wTh;
        unsigned long long acc[4][2];
        #pragma unroll
        for (int li = 0; li < 4; li++) { acc[li][0] = 0ull; acc[li][1] = 0ull; }

        const int kp0 = q * 40;
        #pragma unroll 5
        for (int kp = kp0; kp < kp0 + 40; kp += 2) {
            const ulonglong2 w0 = *(const ulonglong2*)&wT[kp * 64 + jj2 * 2];
            const ulonglong2 w1 = *(const ulonglong2*)&wT[(kp + 1) * 64 + jj2 * 2];
            const int k = kp * 2;   // 4 ks: k..k+3 (never straddles 256)
            #pragma unroll
            for (int li = 0; li < 4; li++) {
                int l = lh * 4 + li;
                ulonglong2 v;
                if (k < 256) v = *(const ulonglong2*)&sg[l * GDIM + 544 + k];
                else         v = *(const ulonglong2*)&sdist[l * 64 + (k - 256)];
                FMA2(acc[li][0], v.x, w0.x);
                FMA2(acc[li][1], v.x, w0.y);
                FMA2(acc[li][0], v.y, w1.x);
                FMA2(acc[li][1], v.y, w1.y);
            }
        }
        #pragma unroll
        for (int li = 0; li < 4; li++) {
            int l = lh * 4 + li;
            float2 a0 = upk(acc[li][0]);
            float2 a1 = upk(acc[li][1]);
            *(float2*)&red[q * 512 + l * 64 + sel * 32 + jj2] =
                make_float2(a0.x + a0.y, a1.x + a1.y);
        }
    }
    __syncthreads();

    // ---- reduce pred partials + bias -> out ----
    #pragma unroll
    for (int rep = 0; rep < 2; rep++) {
        int p = rep * NTHR + t;
        int l = p >> 6, j = p & 63, jj = j & 31;
        float s = (red[0 * 512 + l * 64 + j] + red[1 * 512 + l * 64 + j])
                + (red[2 * 512 + l * 64 + j] + red[3 * 512 + l * 64 + j]);
        int b = b0 + l;
        if (b < B) {
            if (j < 32) out[B + (long)b * 32 + jj] = s + headb[jj];
            else        out[B + (long)B * 32 + (long)b * 32 + jj] = s + tailb[jj];
        }
    }
    __syncthreads();   // red reused below

    // ---- W1: g_rep[864] @ W1[864,64], f32x2 k-paired ----
    // thread = (j2:32, q:4, lh:2); 4 links, 2 j, 216 ks (108 kpairs)
    {
        const int j2 = (t & 31) * 2;
        const int q  = (t >> 5) & 3;
        const int lh = t >> 7;
        unsigned long long acc[4][2];
        #pragma unroll
        for (int li = 0; li < 4; li++) { acc[li][0] = 0ull; acc[li][1] = 0ull; }

        const int kp0 = q * 108;
        #pragma unroll 3
        for (int kp = kp0; kp < kp0 + 108; kp += 2) {
            const ulonglong2 w0 = *(const ulonglong2*)&g_wT1[kp * 128 + j2 * 2];
            const ulonglong2 w1 = *(const ulonglong2*)&g_wT1[(kp + 1) * 128 + j2 * 2];
            const int k = kp * 2;
            #pragma unroll
            for (int li = 0; li < 4; li++) {
                int l = lh * 4 + li;
                const ulonglong2 v = *(const ulonglong2*)&sg[l * GDIM + k];
                FMA2(acc[li][0], v.x, w0.x);
                FMA2(acc[li][1], v.x, w0.y);
                FMA2(acc[li][0], v.y, w1.x);
                FMA2(acc[li][1], v.y, w1.y);
            }
        }
        #pragma unroll
        for (int li = 0; li < 4; li++) {
            int l = lh * 4 + li;
            float2 a0 = upk(acc[li][0]);
            float2 a1 = upk(acc[li][1]);
            *(float2*)&red[q * 512 + l * 64 + j2] =
                make_float2(a0.x + a0.y, a1.x + a1.y);
        }
    }
    __syncthreads();

    // ---- reduce W1 partials + bias + relu -> sh1 ----
    #pragma unroll
    for (int rep = 0; rep < 2; rep++) {
        int p = rep * NTHR + t;
        int l = p >> 6, j = p & 63;
        float s = (red[0 * 512 + l * 64 + j] + red[1 * 512 + l * 64 + j])
                + (red[2 * 512 + l * 64 + j] + red[3 * 512 + l * 64 + j]);
        sh1[l * 64 + j] = fmaxf(s + b1[j], 0.f);
    }
    __syncthreads();

    // ---- W2: h1[64] @ W2[64,32] + relu (LPB*32 == NTHR) ----
    {
        int j = t & 31, l = t >> 5;
        float a = 0.f;
        #pragma unroll
        for (int k = 0; k < 64; k += 4) {
            float w0 = W2[(k    ) * 32 + j];
            float w1 = W2[(k + 1) * 32 + j];
            float w2 = W2[(k + 2) * 32 + j];
            float w3 = W2[(k + 3) * 32 + j];
            const float4 h = *(const float4*)&sh1[l * 64 + k];
            a = fmaf(h.x, w0, a);
            a = fmaf(h.y, w1, a);
            a = fmaf(h.z, w2, a);
            a = fmaf(h.w, w3, a);
        }
        sh2[l * 32 + j] = fmaxf(a + b2[j], 0.f);
    }
    __syncthreads();

    // ---- W3: h2[32] @ W3[32,1] -> out[b] (8 warps, 1 link each) ----
    {
        int w = t >> 5, lane = t & 31;
        float v = sh2[w * 32 + lane] * W3[lane];
        #pragma unroll
        for (int off = 16; off > 0; off >>= 1)
            v += __shfl_xor_sync(0xFFFFFFFFu, v, off);
        if (lane == 0 && (b0 + w) < B)
            out[b0 + w] = v + b3[0];
    }
}

extern "C" void kernel_launch(void* const* d_in, const int* in_sizes, int n_in,
                              void* d_out, int out_size)
{
    const float* flat     = (const float*)d_in[0];
    const float* feat     = (const float*)d_in[1];
    const int*   head_idx = (const int*)  d_in[2];
    const int*   rel_idx  = (const int*)  d_in[3];
    const int*   tail_idx = (const int*)  d_in[4];
    const int*   dist_idx = (const int*)  d_in[5];
    const int*   inter    = (const int*)  d_in[6];
    const float* rel_emb  = (const float*)d_in[7];
    const float* dist_emb = (const float*)d_in[8];
    const float* headW    = (const float*)d_in[9];
    const float* headb    = (const float*)d_in[10];
    const float* tailW    = (const float*)d_in[11];
    const float* tailb    = (const float*)d_in[12];
    const float* W1       = (const float*)d_in[13];
    const float* b1       = (const float*)d_in[14];
    const float* W2       = (const float*)d_in[15];
    const float* b2       = (const float*)d_in[16];
    const float* W3       = (const float*)d_in[17];
    const float* b3       = (const float*)d_in[18];

    int B = in_sizes[2];   // head_idx element count

    // one-time weight transpose into k-paired layouts
    int prep_total = 432 * 128 + 2 * 160 * 64;
    gcw_prep<<<(prep_total + 255) / 256, 256>>>(W1, headW, tailW);

    cudaFuncSetAttribute(gcw_fused, cudaFuncAttributeMaxDynamicSharedMemorySize, SMEM_BYTES);

    int grid = (B + LPB - 1) / LPB;
    gcw_fused<<<grid, NTHR, SMEM_BYTES>>>(
        flat, feat, head_idx, rel_idx, tail_idx, dist_idx, inter,
        rel_emb, dist_emb, headb, tailb,
        b1, W2, b2, W3, b3,
        (float*)d_out, B);
}